// round 3
// baseline (speedup 1.0000x reference)
#include <cuda_runtime.h>
#include <cuda_bf16.h>
#include <cstdint>

// Problem constants (fixed by the dataset): B=64, T=12, C=64, SIDE=32, S2=1024.
#define PB   64
#define PT   12
#define PC   64
#define PS2  1024
#define ROWS (PB * PC)        // 4096 (b,c) rows in the last-T slice
#define ROWS_PER_RBLK 16      // reduce: rows per block

// Scratch (no device allocation allowed): per-cell nonzero flags + int32 poi.
__device__ __align__(16) int g_nz[PS2];
__device__ __align__(16) int g_poi[PS2];

// Kernel 1: column-OR reduce of mask slice m[:, T-1] over all 4096 rows.
// Each block: 256 threads x int4 covers all 1024 columns; loops 16 rows.
// Block 0 additionally converts poi_index (dtype auto-detect int32 vs int64:
// JAX under default config silently narrows jnp.int64 -> int32).
__global__ void reduce_kernel(const int* __restrict__ m,
                              const int* __restrict__ poi_words) {
    const int t = threadIdx.x;            // 0..255
    const int row0 = blockIdx.x * ROWS_PER_RBLK;
    int4 acc = make_int4(0, 0, 0, 0);
#pragma unroll
    for (int i = 0; i < ROWS_PER_RBLK; i++) {
        const int row = row0 + i;
        const int b = row >> 6;
        const int c = row & 63;
        const size_t base = ((size_t)(b * PT + (PT - 1)) * PC + c) * PS2;
        const int4 v = *(const int4*)(m + base + 4 * t);
        acc.x |= v.x; acc.y |= v.y; acc.z |= v.z; acc.w |= v.w;
    }
    // Only touch flags that are actually nonzero (halves atomic traffic:
    // even cells are forced-zero by the reference's cell_keep).
    if (acc.x) atomicOr(&g_nz[4 * t + 0], 1);
    if (acc.y) atomicOr(&g_nz[4 * t + 1], 1);
    if (acc.z) atomicOr(&g_nz[4 * t + 2], 1);
    if (acc.w) atomicOr(&g_nz[4 * t + 3], 1);

    if (blockIdx.x == 0) {
        // poi dtype detection: read ONLY the first 1024 words (safe for both
        // dtypes). int64 little-endian with values < 1024 => all odd words 0.
        __shared__ int odd_nonzero;
        if (t == 0) odd_nonzero = 0;
        const int4 w = ((const int4*)poi_words)[t];   // words 4t..4t+3
        __syncthreads();
        if (w.y | w.w) atomicOr(&odd_nonzero, 1);
        __syncthreads();
        if (odd_nonzero) {
            // genuine int32 buffer: word i IS poi[i]
            ((int4*)g_poi)[t] = w;
        } else {
            // int64 buffer: value i lives at word 2i (8 KiB buffer, in-bounds)
            const int4 a = ((const int4*)poi_words)[2 * t];      // words 8t..8t+3
            const int4 b = ((const int4*)poi_words)[2 * t + 1];  // words 8t+4..8t+7
            ((int4*)g_poi)[t] = make_int4(a.x, a.z, b.x, b.z);
        }
    }
}

// Kernel 2: out[row, s] = data[row, s] + (empty[s] ? data[row, poi[s]] : 0).
// One block per (b,c) row; row staged in shared so the random gather is an LDS.
__global__ void apply_kernel(const float* __restrict__ d, float* __restrict__ out) {
    __shared__ float row_s[PS2];
    const int t = threadIdx.x;            // 0..255
    const int row = blockIdx.x;           // 0..4095
    const int b = row >> 6;
    const int c = row & 63;
    const size_t base = ((size_t)(b * PT + (PT - 1)) * PC + c) * PS2;

    float4 v = *(const float4*)(d + base + 4 * t);
    ((float4*)row_s)[t] = v;

    const int4 nz = ((const int4*)g_nz)[t];
    const int4 pi = ((const int4*)g_poi)[t];
    __syncthreads();

    if (!nz.x) v.x += row_s[pi.x];
    if (!nz.y) v.y += row_s[pi.y];
    if (!nz.z) v.z += row_s[pi.z];
    if (!nz.w) v.w += row_s[pi.w];

    ((float4*)out)[(size_t)row * (PS2 / 4) + t] = v;
}

extern "C" void kernel_launch(void* const* d_in, const int* in_sizes, int n_in,
                              void* d_out, int out_size) {
    const float* d   = (const float*)d_in[0];
    const int*   m   = (const int*)d_in[1];
    const int*   poi = (const int*)d_in[2];   // int32 or int64 words, auto-detected
    // d_in[3] = side (constant 32), unused.
    float* out = (float*)d_out;

    // Zero the per-cell flags via a graph memset node (replaces init_kernel).
    void* nz_ptr = nullptr;
    cudaGetSymbolAddress(&nz_ptr, g_nz);
    cudaMemsetAsync(nz_ptr, 0, PS2 * sizeof(int), 0);

    reduce_kernel<<<ROWS / ROWS_PER_RBLK, 256>>>(m, poi);
    apply_kernel<<<ROWS, 256>>>(d, out);
}

// round 4
// speedup vs baseline: 1.0393x; 1.0393x over previous
#include <cuda_runtime.h>
#include <cuda_bf16.h>
#include <cstdint>

// Problem constants (fixed by the dataset): B=64, T=12, C=64, SIDE=32, S2=1024.
#define PB   64
#define PT   12
#define PC   64
#define PS2  1024
#define ROWS (PB * PC)          // 4096 (b,c) rows in the last-T slice

#define RBLOCKS 32              // reduce blocks; each owns 32 columns
#define COLS_PER_RBLK 32
#define ROWS_PER_ABLK 4         // apply: rows per block

// Scratch (no device allocation allowed): per-cell nonzero flags + int32 poi.
// Written fresh by reduce_kernel every launch (plain stores — no init needed).
__device__ __align__(16) int g_nz[PS2];
__device__ __align__(16) int g_poi[PS2];

// Kernel 1: column-OR reduce of mask slice m[:, T-1].
// Each block owns 32 columns over all 4096 rows (512 KB), reads 128B/row chunks
// (full L1-line coalescing), tree-reduces in smem, writes flags with plain
// stores. Block 0 additionally converts poi_index (dtype auto-detect: JAX under
// default config silently narrows jnp.int64 -> int32).
__global__ void __launch_bounds__(256) reduce_kernel(const int* __restrict__ m,
                                                     const int* __restrict__ poi_words) {
#if __CUDA_ARCH__ >= 900
    cudaTriggerProgrammaticLaunchCompletion();   // let apply start loading now
#endif
    const int t = threadIdx.x;
    const int c0 = blockIdx.x * COLS_PER_RBLK;
    const int lane8 = t & 7;     // which int4 within the 32-col chunk
    const int rbase = t >> 3;    // 0..31 row-in-iteration

    int4 acc = make_int4(0, 0, 0, 0);
#pragma unroll 4
    for (int it = 0; it < ROWS / 32; ++it) {     // 128 iterations
        const int row = it * 32 + rbase;
        const int b = row >> 6;
        const int c = row & 63;
        const size_t base = ((size_t)(b * PT + (PT - 1)) * PC + c) * PS2;
        const int4 v = *(const int4*)(m + base + c0 + 4 * lane8);
        acc.x |= v.x; acc.y |= v.y; acc.z |= v.z; acc.w |= v.w;
    }

    __shared__ int4 red[256];
    red[t] = acc;
    __syncthreads();
    // fold the row dimension (high bits of t) down onto the 8 lane slots
#pragma unroll
    for (int s = 128; s >= 8; s >>= 1) {
        if (t < s) {
            int4 a = red[t], o = red[t + s];
            a.x |= o.x; a.y |= o.y; a.z |= o.z; a.w |= o.w;
            red[t] = a;
        }
        __syncthreads();
    }
    if (t < 8) ((int4*)(g_nz + c0))[t] = red[t];

    if (blockIdx.x == 0) {
        // poi dtype detection: read ONLY the first 1024 words (safe for both
        // dtypes). int64 little-endian with values < 1024 => all odd words 0.
        __shared__ int odd_nonzero;
        if (t == 0) odd_nonzero = 0;
        const int4 w = ((const int4*)poi_words)[t];     // words 4t..4t+3
        __syncthreads();
        if (w.y | w.w) atomicOr(&odd_nonzero, 1);
        __syncthreads();
        if (odd_nonzero) {
            ((int4*)g_poi)[t] = w;                       // genuine int32
        } else {
            const int4 a  = ((const int4*)poi_words)[2 * t];
            const int4 b2 = ((const int4*)poi_words)[2 * t + 1];
            ((int4*)g_poi)[t] = make_int4(a.x, a.z, b2.x, b2.z);  // int64 lo-words
        }
    }
}

// Kernel 2: out[row, s] = data[row, s] + (empty[s] ? data[row, poi[s]] : 0).
// 4 rows per block (MLP=4); rows staged in shared so the random gather is LDS.
// Launched with programmatic stream serialization: loads start while reduce
// still runs; flags/poi only read after cudaGridDependencySynchronize().
__global__ void __launch_bounds__(256) apply_kernel(const float* __restrict__ d,
                                                    float* __restrict__ out) {
    __shared__ float rs[ROWS_PER_ABLK][PS2];
    const int t = threadIdx.x;
    const int row0 = blockIdx.x * ROWS_PER_ABLK;     // 4 | 64 => same b for all 4
    const int b = row0 >> 6;
    const int c00 = row0 & 63;
    const float* src = d + ((size_t)(b * PT + (PT - 1)) * PC + c00) * PS2;

    float4 v[ROWS_PER_ABLK];
#pragma unroll
    for (int r = 0; r < ROWS_PER_ABLK; r++)
        v[r] = *(const float4*)(src + r * PS2 + 4 * t);
#pragma unroll
    for (int r = 0; r < ROWS_PER_ABLK; r++)
        ((float4*)rs[r])[t] = v[r];

#if __CUDA_ARCH__ >= 900
    cudaGridDependencySynchronize();                  // reduce results now visible
#endif
    const int4 nz = ((const int4*)g_nz)[t];
    const int4 pi = ((const int4*)g_poi)[t];
    __syncthreads();

#pragma unroll
    for (int r = 0; r < ROWS_PER_ABLK; r++) {
        if (!nz.x) v[r].x += rs[r][pi.x];
        if (!nz.y) v[r].y += rs[r][pi.y];
        if (!nz.z) v[r].z += rs[r][pi.z];
        if (!nz.w) v[r].w += rs[r][pi.w];
    }

    float4* dst = (float4*)(out + (size_t)row0 * PS2);
#pragma unroll
    for (int r = 0; r < ROWS_PER_ABLK; r++)
        dst[r * (PS2 / 4) + t] = v[r];
}

extern "C" void kernel_launch(void* const* d_in, const int* in_sizes, int n_in,
                              void* d_out, int out_size) {
    const float* d   = (const float*)d_in[0];
    const int*   m   = (const int*)d_in[1];
    const int*   poi = (const int*)d_in[2];   // int32 or int64 words, auto-detected
    // d_in[3] = side (constant 32), unused.
    float* out = (float*)d_out;

    reduce_kernel<<<RBLOCKS, 256>>>(m, poi);

    // apply: PDL secondary — may start before reduce finishes; it synchronizes
    // internally via cudaGridDependencySynchronize before reading flags.
    cudaLaunchConfig_t cfg = {};
    cfg.gridDim  = dim3(ROWS / ROWS_PER_ABLK, 1, 1);
    cfg.blockDim = dim3(256, 1, 1);
    cfg.dynamicSmemBytes = 0;
    cudaLaunchAttribute attrs[1];
    attrs[0].id = cudaLaunchAttributeProgrammaticStreamSerialization;
    attrs[0].val.programmaticStreamSerializationAllowed = 1;
    cfg.attrs = attrs;
    cfg.numAttrs = 1;
    cudaLaunchKernelEx(&cfg, apply_kernel, d, out);
}

// round 5
// speedup vs baseline: 1.1783x; 1.1338x over previous
#include <cuda_runtime.h>
#include <cuda_bf16.h>
#include <cstdint>

// Problem constants (fixed by the dataset): B=64, T=12, C=64, SIDE=32, S2=1024.
#define PB   64
#define PT   12
#define PC   64
#define PS2  1024
#define ROWS (PB * PC)          // 4096 (b,c) rows in the last-T slice

#define GRID  512               // blocks; all co-resident (<= 148*4) => spin barrier safe
#define RPB   8                 // rows per block (8 | 64 => same b within a block)

// Persistent scratch (module-load zero-initialized; each launch restores zeros
// in its epilogue, so every call is identical => graph-replay deterministic).
__device__ int g_poi[PS2];
__device__ unsigned g_maskpad[32 * 64];   // word i at [i*64]: 256B stride => spread LTS slices
__device__ int g_c0;                      // barrier arrival counter
__device__ int g_c1;                      // epilogue counter (last block resets state)

__global__ void __launch_bounds__(256, 4)
fused_kernel(const float* __restrict__ d, const int* __restrict__ m,
             const int* __restrict__ poi_words, float* __restrict__ out) {
    __shared__ float    rs[RPB][PS2];     // 32 KB: staged d rows
    __shared__ unsigned smask[32];        // block-partial 1024-bit mask
    __shared__ unsigned smw[32];          // final mask words
    __shared__ int      sh_odd;           // poi dtype detector (block 0)

    const int t = threadIdx.x;            // 0..255
    const int g = blockIdx.x;             // 0..511
    const int row0 = g * RPB;
    const int b  = row0 >> 6;
    const int cc = row0 & 63;
    const size_t base = ((size_t)(b * PT + (PT - 1)) * PC + cc) * PS2;

    if (t == 0) sh_odd = 0;
    if (t < 32) smask[t] = 0;

    // ---- phase 1: OR-reduce this block's 8 mask rows (columns 4t..4t+3) ----
    const int* msrc = m + base;
    int4 acc = make_int4(0, 0, 0, 0);
#pragma unroll
    for (int r = 0; r < RPB; r++) {
        const int4 v = *(const int4*)(msrc + r * PS2 + 4 * t);
        acc.x |= v.x; acc.y |= v.y; acc.z |= v.z; acc.w |= v.w;
    }
    const unsigned nib = (acc.x ? 1u : 0u) | (acc.y ? 2u : 0u)
                       | (acc.z ? 4u : 0u) | (acc.w ? 8u : 0u);

    // block 0: poi dtype detect (JAX silently narrows jnp.int64 -> int32).
    // Read ONLY the first 1024 words (safe for both dtypes); int64 little-endian
    // with values < 1024 => all odd words zero.
    int4 w = make_int4(0, 0, 0, 0);
    if (g == 0) {
        w = ((const int4*)poi_words)[t];
        if (w.y | w.w) atomicOr(&sh_odd, 1);
    }

    // ---- overlap: stage this block's 8 d rows into smem (hides barrier) ----
    const float* dsrc = d + base;
    float4 v[RPB];
#pragma unroll
    for (int r = 0; r < RPB; r++)
        v[r] = *(const float4*)(dsrc + r * PS2 + 4 * t);
#pragma unroll
    for (int r = 0; r < RPB; r++)
        ((float4*)rs[r])[t] = v[r];

    __syncthreads();                                  // smask init, sh_odd final
    if (nib) atomicOr(&smask[t >> 3], nib << ((t & 7) * 4));
    if (g == 0) {
        if (sh_odd) {
            ((int4*)g_poi)[t] = w;                    // genuine int32
        } else {
            const int4 p0 = ((const int4*)poi_words)[2 * t];
            const int4 p1 = ((const int4*)poi_words)[2 * t + 1];
            ((int4*)g_poi)[t] = make_int4(p0.x, p0.z, p1.x, p1.z);
        }
    }
    __syncthreads();                                  // smask final
    if (t < 32 && smask[t]) atomicOr(&g_maskpad[t << 6], smask[t]);
    __threadfence();                                  // release partials + poi
    __syncthreads();

    // ---- grid-wide barrier (all GRID blocks co-resident => safe) ----
    if (t == 0) {
        atomicAdd(&g_c0, 1);
        volatile int* vc = &g_c0;
        while (*vc < GRID) {
#if __CUDA_ARCH__ >= 700
            __nanosleep(64);
#endif
        }
    }
    __syncthreads();
    __threadfence();                                  // acquire

    // ---- phase 2: gather + add + store ----
    if (t < 32) smw[t] = g_maskpad[t << 6];
    const int4 pi = ((const int4*)g_poi)[t];
    __syncthreads();
    const unsigned nib2 = (smw[t >> 3] >> ((t & 7) * 4)) & 0xFu;  // 1 = nonzero cell

#pragma unroll
    for (int r = 0; r < RPB; r++) {
        if (!(nib2 & 1u)) v[r].x += rs[r][pi.x];
        if (!(nib2 & 2u)) v[r].y += rs[r][pi.y];
        if (!(nib2 & 4u)) v[r].z += rs[r][pi.z];
        if (!(nib2 & 8u)) v[r].w += rs[r][pi.w];
    }
    float4* dst = (float4*)(out + (size_t)row0 * PS2);
#pragma unroll
    for (int r = 0; r < RPB; r++)
        dst[r * (PS2 / 4) + t] = v[r];

    // ---- epilogue: last block restores zeros for the next (graph) replay ----
    if (t == 0) {
        __threadfence();
        const int r = atomicAdd(&g_c1, 1);
        if (r == GRID - 1) {
#pragma unroll
            for (int i = 0; i < 32; i++) g_maskpad[i << 6] = 0;
            g_c0 = 0;
            g_c1 = 0;
            __threadfence();
        }
    }
}

extern "C" void kernel_launch(void* const* d_in, const int* in_sizes, int n_in,
                              void* d_out, int out_size) {
    const float* d   = (const float*)d_in[0];
    const int*   m   = (const int*)d_in[1];
    const int*   poi = (const int*)d_in[2];   // int32 or int64 words, auto-detected
    // d_in[3] = side (constant 32), unused.
    float* out = (float*)d_out;

    fused_kernel<<<GRID, 256>>>(d, m, poi, out);
}